// round 12
// baseline (speedup 1.0000x reference)
#include <cuda_runtime.h>
#include <cuda_bf16.h>

// ChamferLoss: fully-fused persistent kernel (single launch).
// P0 zero/init -> P1 morton+hist -> P2 local scan -> P2b prefix+offsets ->
// P3 scatter -> P4 group AABBs + seed evals -> P5 smem AABBs -> P6 queue sweep
// -> ticket reduce (graph-replay safe).
// L1-cached loads for g_sorted/g_gaabb are safe: L1 flushed per launch and
// nothing reads these arrays before their writing phase. Pruning conservative
// -> exact mins (min over any superset containing true NN = true min).

#define NPTS   16384
#define NBINS  32768
#define NGRP   512
#define NSUP   64
#define NUNITS (2 * NGRP)     // 1024: unit = (dir, xgroup)
#define NBLK   148
#define NTHR   1024

#define INFF __int_as_float(0x7f800000)

__device__ float4   g_sorted[2][NPTS];
__device__ unsigned g_hist[2 * NBINS];
__device__ unsigned g_offs[2 * NBINS];
__device__ unsigned g_part[128];
__device__ float4   g_gaabb[2][NGRP][2];
__device__ unsigned g_minbits[2][NPTS];
__device__ unsigned g_bar, g_work, g_done;

__device__ __forceinline__ unsigned spread5(unsigned v) {
    return (v & 1u) | ((v & 2u) << 2) | ((v & 4u) << 4) |
           ((v & 8u) << 6) | ((v & 16u) << 8);
}
__device__ __forceinline__ unsigned morton(float x, float y, float z) {
    int qx = (int)((x + 5.0f) * 3.2f); qx = max(0, min(31, qx));
    int qy = (int)((y + 5.0f) * 3.2f); qy = max(0, min(31, qy));
    int qz = (int)((z + 5.0f) * 3.2f); qz = max(0, min(31, qz));
    return spread5((unsigned)qx) | (spread5((unsigned)qy) << 1) | (spread5((unsigned)qz) << 2);
}

__device__ __forceinline__ void gsync(unsigned target) {
    __syncthreads();
    if (threadIdx.x == 0) {
        __threadfence();
        atomicAdd(&g_bar, 1u);
        while (atomicAdd(&g_bar, 0u) < target) __nanosleep(64);
    }
    __syncthreads();
}

__device__ __forceinline__ float boxd2(float px, float py, float pz,
                                       float4 lo, float4 hi) {
    float dx = fmaxf(fmaxf(lo.x - px, px - hi.x), 0.0f);
    float dy = fmaxf(fmaxf(lo.y - py, py - hi.y), 0.0f);
    float dz = fmaxf(fmaxf(lo.z - pz, pz - hi.z), 0.0f);
    return fmaf(dx, dx, fmaf(dy, dy, dz * dz));
}

// Warp-uniform cached loads (broadcast, L1-resident after first touch).
#define EVAL_GROUP(SY, G)                                          \
    do {                                                           \
        const float4* yg = &g_sorted[SY][(G) * 32];                \
        _Pragma("unroll")                                          \
        for (int i2 = 0; i2 < 32; i2 += 2) {                       \
            float4 ya = yg[i2];                                    \
            float4 yb = yg[i2 + 1];                                \
            float ta = fmaf(-xp.x, ya.x, ya.w);                    \
            ta = fmaf(-xp.y, ya.y, ta);                            \
            ta = fmaf(-xp.z, ya.z, ta);                            \
            ma = fminf(ma, ta);                                    \
            float tb = fmaf(-xp.x, yb.x, yb.w);                    \
            tb = fmaf(-xp.y, yb.y, tb);                            \
            tb = fmaf(-xp.z, yb.z, tb);                            \
            mb = fminf(mb, tb);                                    \
        }                                                          \
    } while (0)

__global__ __launch_bounds__(NTHR, 1) void k_all(const float* __restrict__ pred,
                                                 const float* __restrict__ gt,
                                                 float* __restrict__ out) {
    __shared__ float4 sb[2][NGRP][2];      // 32 KB group AABBs
    __shared__ float4 ssb[2][NSUP][2];     // 4 KB supergroup AABBs
    __shared__ __align__(16) unsigned char scratch[4096];  // sscan | red
    __shared__ unsigned s_ticket;
    unsigned* sscan = (unsigned*)scratch;
    float*    red   = (float*)scratch;

    const int tid  = threadIdx.x;
    const int bid  = blockIdx.x;
    const int gi   = bid * NTHR + tid;
    const int lane = tid & 31;
    const int wid  = tid >> 5;
    const int gw   = bid * (NTHR / 32) + wid;

    // ---- P0: zero hist, init minbits ----
    if (gi < 2 * NBINS) g_hist[gi] = 0;
    if (gi < 2 * NPTS) (&g_minbits[0][0])[gi] = 0x7f800000u;
    gsync(1 * NBLK);

    // ---- P1: code + histogram (item kept in registers through P3) ----
    int my_s = -1;
    unsigned my_c = 0;
    float mx = 0.f, myy = 0.f, mz = 0.f;
    if (gi < 2 * NPTS) {
        my_s = gi >> 14;
        int p = gi & (NPTS - 1);
        const float* src = my_s ? gt : pred;
        mx = src[3 * p]; myy = src[3 * p + 1]; mz = src[3 * p + 2];
        my_c = morton(mx, myy, mz);
        atomicAdd(&g_hist[my_s * NBINS + my_c], 1u);
    }
    gsync(2 * NBLK);

    // ---- P2: block-local exclusive scan (128 blocks x 512 bins) ----
    unsigned lexcl = 0;
    if (bid < 128) {
        unsigned h = (tid < 512) ? __ldcg(&g_hist[bid * 512 + tid]) : 0u;
        if (tid < 512) sscan[tid] = h;
        __syncthreads();
        for (int d = 1; d < 512; d <<= 1) {
            unsigned v = (tid >= d && tid < 512) ? sscan[tid - d] : 0u;
            __syncthreads();
            if (tid < 512) sscan[tid] += v;
            __syncthreads();
        }
        if (tid < 512) lexcl = sscan[tid] - h;
        if (tid == 511) g_part[bid] = sscan[511];
    }
    gsync(3 * NBLK);

    // ---- P2b: chunk prefixes + offsets (set1 adjusted by -NPTS) ----
    if (bid < 128) {
        if (tid < 128) sscan[tid] = __ldcg(&g_part[tid]);
        __syncthreads();
        for (int d = 1; d < 128; d <<= 1) {
            unsigned v = (tid >= d && tid < 128) ? sscan[tid - d] : 0u;
            __syncthreads();
            if (tid < 128) sscan[tid] += v;
            __syncthreads();
        }
        unsigned prefix = (bid == 0) ? 0u : sscan[bid - 1];
        unsigned adj = (bid >= 64) ? (unsigned)NPTS : 0u;
        if (tid < 512) g_offs[bid * 512 + tid] = lexcl + prefix - adj;
    }
    gsync(4 * NBLK);

    // ---- P3: scatter ----
    if (my_s >= 0) {
        unsigned pos = atomicAdd(&g_offs[my_s * NBINS + my_c], 1u);
        g_sorted[my_s][pos] =
            make_float4(mx, myy, mz, 0.5f * (mx * mx + myy * myy + mz * mz));
    }
    gsync(5 * NBLK);

    // ---- P4: group AABBs (warps 0..1023) + seed evals (warps 1024..2047) ----
    if (gw < 2 * NGRP) {
        int s = gw >= NGRP, g = gw & (NGRP - 1);
        float4 pv = g_sorted[s][g * 32 + lane];
        float lx = pv.x, ly = pv.y, lz = pv.z;
        float hx = pv.x, hy = pv.y, hz = pv.z;
#pragma unroll
        for (int d = 16; d > 0; d >>= 1) {
            lx = fminf(lx, __shfl_xor_sync(0xffffffffu, lx, d));
            ly = fminf(ly, __shfl_xor_sync(0xffffffffu, ly, d));
            lz = fminf(lz, __shfl_xor_sync(0xffffffffu, lz, d));
            hx = fmaxf(hx, __shfl_xor_sync(0xffffffffu, hx, d));
            hy = fmaxf(hy, __shfl_xor_sync(0xffffffffu, hy, d));
            hz = fmaxf(hz, __shfl_xor_sync(0xffffffffu, hz, d));
        }
        if (lane == 0) {
            g_gaabb[s][g][0] = make_float4(lx, ly, lz, 0.0f);
            g_gaabb[s][g][1] = make_float4(hx, hy, hz, 0.0f);
        }
    } else if (gw < 4 * NGRP) {
        int id = gw - 2 * NGRP;
        int dir = id >= NGRP, xg = id & (NGRP - 1);
        int sy = dir ^ 1;
        float4 xp = g_sorted[dir][xg * 32 + lane];
        float x2 = 2.0f * xp.w;
        float ma = INFF, mb = INFF;
        int s0 = max(xg - 1, 0), s1 = min(xg + 1, NGRP - 1);
        for (int g = s0; g <= s1; ++g) EVAL_GROUP(sy, g);
        float d2 = fmaxf(fmaf(2.0f, fminf(ma, mb), x2), 0.0f);
        atomicMin(&g_minbits[dir][xg * 32 + lane], __float_as_uint(d2));
    }
    gsync(6 * NBLK);

    // ---- P5: AABBs into smem (block-local) ----
    for (int i = tid; i < 2 * NGRP; i += NTHR) {
        int s = i >= NGRP, g = i & (NGRP - 1);
        sb[s][g][0] = g_gaabb[s][g][0];
        sb[s][g][1] = g_gaabb[s][g][1];
    }
    __syncthreads();
    if (tid < 2 * NSUP) {
        int s = tid >= NSUP, i = tid & (NSUP - 1);
        float4 lo = sb[s][i * 8][0];
        float4 hi = sb[s][i * 8][1];
#pragma unroll
        for (int k = 1; k < 8; ++k) {
            float4 a = sb[s][i * 8 + k][0];
            float4 b = sb[s][i * 8 + k][1];
            lo.x = fminf(lo.x, a.x); lo.y = fminf(lo.y, a.y); lo.z = fminf(lo.z, a.z);
            hi.x = fmaxf(hi.x, b.x); hi.y = fmaxf(hi.y, b.y); hi.z = fmaxf(hi.z, b.z);
        }
        ssb[s][i][0] = lo;
        ssb[s][i][1] = hi;
    }
    __syncthreads();

    // ---- P6: work-queue pruned sweep (unit = dir,xgroup) ----
    for (;;) {
        unsigned uid;
        if (lane == 0) uid = atomicAdd(&g_work, 1u);
        uid = __shfl_sync(0xffffffffu, uid, 0);
        if (uid >= NUNITS) break;

        const int dir = uid & 1;
        const int xg  = uid >> 1;
        const int sy  = dir ^ 1;
        const int s0 = max(xg - 1, 0), s1 = min(xg + 1, NGRP - 1);

        const float4 xp = g_sorted[dir][xg * 32 + lane];
        const float x2 = 2.0f * xp.w;
        float ub2 = __uint_as_float(__ldcg(&g_minbits[dir][xg * 32 + lane]));
        float ma = INFF, mb = INFF;

        for (int sg = 0; sg < NSUP; ++sg) {
            bool hit = boxd2(xp.x, xp.y, xp.z, ssb[sy][sg][0], ssb[sy][sg][1]) <= ub2;
            if (!__any_sync(0xffffffffu, hit)) continue;
            unsigned gm = 0;
#pragma unroll
            for (int b = 0; b < 8; ++b) {
                int g = sg * 8 + b;
                if (boxd2(xp.x, xp.y, xp.z, sb[sy][g][0], sb[sy][g][1]) <= ub2)
                    gm |= 1u << b;
            }
            gm = __reduce_or_sync(0xffffffffu, gm);
            while (gm) {
                int b = __ffs(gm) - 1;
                gm &= gm - 1;
                int g = sg * 8 + b;
                if (g >= s0 && g <= s1) continue;   // seeds already evaluated
                EVAL_GROUP(sy, g);
                ub2 = fminf(ub2, fmaxf(fmaf(2.0f, fminf(ma, mb), x2), 0.0f));
            }
        }
        if (fminf(ma, mb) < INFF) {
            float d2 = fmaxf(fmaf(2.0f, fminf(ma, mb), x2), 0.0f);
            atomicMin(&g_minbits[dir][xg * 32 + lane], __float_as_uint(d2));
        }
    }

    // ---- ticket: last block reduces + resets counters ----
    __threadfence();
    __syncthreads();
    if (tid == 0) s_ticket = atomicAdd(&g_done, 1u);
    __syncthreads();
    if (s_ticket == NBLK - 1) {
        if (tid == 0) { g_bar = 0; g_work = 0; g_done = 0; }
        __threadfence();
        float s = 0.0f;
        const unsigned* mb32 = &g_minbits[0][0];
        for (int i = tid; i < 2 * NPTS; i += NTHR)
            s += sqrtf(__uint_as_float(__ldcg(&mb32[i])));
        red[tid] = s;
        __syncthreads();
        for (int w = NTHR / 2; w > 0; w >>= 1) {
            if (tid < w) red[tid] += red[tid + w];
            __syncthreads();
        }
        if (tid == 0) out[0] = red[0] * (1.0f / (float)NPTS);
    }
}

extern "C" void kernel_launch(void* const* d_in, const int* in_sizes, int n_in,
                              void* d_out, int out_size) {
    const float* pred = (const float*)d_in[0];
    const float* gt   = (const float*)d_in[1];
    float* out = (float*)d_out;
    k_all<<<NBLK, NTHR>>>(pred, gt, out);
}

// round 14
// speedup vs baseline: 2.0606x; 2.0606x over previous
#include <cuda_runtime.h>
#include <cuda_bf16.h>

// ChamferLoss: fully-fused persistent kernel (single launch).
// P0 zero/init -> P1 morton+hist -> P2 local scan -> P2b prefix -> P3 scatter
// -> P4 group AABBs + seed evals -> P5 smem AABBs -> P6 queue sweep
// -> ticket reduce (graph-replay safe).
// Sweep unit = (dir, xg-pair, ychunk): staged y-tiles amortized over 64
// x-points (2 per lane). Pruning conservative -> exact mins.
// gsync polls via VOLATILE load (a __ldcg poll can be hoisted -> hang).

#define NPTS   16384
#define NBINS  32768
#define NGRP   512
#define NSUP   64
#define NXP    256                 // xg pairs per dir
#define NUNITS (2 * NXP * 8)       // 4096
#define NBLK   148
#define NTHR   1024

#define INFF __int_as_float(0x7f800000)

__device__ float4   g_sorted[2][NPTS];
__device__ unsigned g_hist[2 * NBINS];
__device__ unsigned g_offs[2 * NBINS];
__device__ unsigned g_part[128];
__device__ float4   g_gaabb[2][NGRP][2];
__device__ unsigned g_minbits[2][NPTS];
__device__ unsigned g_bar, g_work, g_done;

__device__ __forceinline__ unsigned spread5(unsigned v) {
    return (v & 1u) | ((v & 2u) << 2) | ((v & 4u) << 4) |
           ((v & 8u) << 6) | ((v & 16u) << 8);
}
__device__ __forceinline__ unsigned morton(float x, float y, float z) {
    int qx = (int)((x + 5.0f) * 3.2f); qx = max(0, min(31, qx));
    int qy = (int)((y + 5.0f) * 3.2f); qy = max(0, min(31, qy));
    int qz = (int)((z + 5.0f) * 3.2f); qz = max(0, min(31, qz));
    return spread5((unsigned)qx) | (spread5((unsigned)qy) << 1) | (spread5((unsigned)qz) << 2);
}

__device__ __forceinline__ void gsync(unsigned target) {
    __syncthreads();
    if (threadIdx.x == 0) {
        __threadfence();
        atomicAdd(&g_bar, 1u);
        while (*((volatile unsigned*)&g_bar) < target) __nanosleep(32);
    }
    __syncthreads();
}

__device__ __forceinline__ float boxd2(float px, float py, float pz,
                                       float4 lo, float4 hi) {
    float dx = fmaxf(fmaxf(lo.x - px, px - hi.x), 0.0f);
    float dy = fmaxf(fmaxf(lo.y - py, py - hi.y), 0.0f);
    float dz = fmaxf(fmaxf(lo.z - pz, pz - hi.z), 0.0f);
    return fmaf(dx, dx, fmaf(dy, dy, dz * dz));
}

// Single-x staged eval (seeds). Coalesced 16-lane stage fill per round.
#define EVAL1(SY, G)                                                          \
    do {                                                                      \
        _Pragma("unroll")                                                     \
        for (int rr = 0; rr < 2; ++rr) {                                      \
            if (lane < 16)                                                    \
                stage[wslot + lane] = g_sorted[SY][(G) * 32 + rr * 16 + lane];\
            __syncwarp();                                                     \
            _Pragma("unroll")                                                 \
            for (int i2 = 0; i2 < 16; i2 += 2) {                              \
                float4 ya = stage[wslot + i2];                                \
                float4 yb = stage[wslot + i2 + 1];                            \
                float t;                                                      \
                t = fmaf(-xp.x, ya.x, ya.w); t = fmaf(-xp.y, ya.y, t);        \
                t = fmaf(-xp.z, ya.z, t);    ma = fminf(ma, t);               \
                t = fmaf(-xp.x, yb.x, yb.w); t = fmaf(-xp.y, yb.y, t);        \
                t = fmaf(-xp.z, yb.z, t);    mb = fminf(mb, t);               \
            }                                                                 \
            __syncwarp();                                                     \
        }                                                                     \
    } while (0)

// Dual-x staged eval (sweep): same staging feeds both register x-points.
#define EVAL2(SY, G)                                                          \
    do {                                                                      \
        _Pragma("unroll")                                                     \
        for (int rr = 0; rr < 2; ++rr) {                                      \
            if (lane < 16)                                                    \
                stage[wslot + lane] = g_sorted[SY][(G) * 32 + rr * 16 + lane];\
            __syncwarp();                                                     \
            _Pragma("unroll")                                                 \
            for (int i2 = 0; i2 < 16; i2 += 2) {                              \
                float4 ya = stage[wslot + i2];                                \
                float4 yb = stage[wslot + i2 + 1];                            \
                float t;                                                      \
                t = fmaf(-xp0.x, ya.x, ya.w); t = fmaf(-xp0.y, ya.y, t);      \
                t = fmaf(-xp0.z, ya.z, t);    ma0 = fminf(ma0, t);            \
                t = fmaf(-xp0.x, yb.x, yb.w); t = fmaf(-xp0.y, yb.y, t);      \
                t = fmaf(-xp0.z, yb.z, t);    mb0 = fminf(mb0, t);            \
                t = fmaf(-xp1.x, ya.x, ya.w); t = fmaf(-xp1.y, ya.y, t);      \
                t = fmaf(-xp1.z, ya.z, t);    ma1 = fminf(ma1, t);            \
                t = fmaf(-xp1.x, yb.x, yb.w); t = fmaf(-xp1.y, yb.y, t);      \
                t = fmaf(-xp1.z, yb.z, t);    mb1 = fminf(mb1, t);            \
            }                                                                 \
            __syncwarp();                                                     \
        }                                                                     \
    } while (0)

__global__ __launch_bounds__(NTHR, 1) void k_all(const float* __restrict__ pred,
                                                 const float* __restrict__ gt,
                                                 float* __restrict__ out) {
    __shared__ float4 sb[2][NGRP][2];              // 32 KB
    __shared__ float4 ssb[2][NSUP][2];             // 4 KB
    __shared__ float4 stage[(NTHR / 32) * 16];     // 8 KB (reduce buf overlaid)
    __shared__ unsigned sscan[512];                // 2 KB
    __shared__ unsigned s_ticket;

    const int tid  = threadIdx.x;
    const int bid  = blockIdx.x;
    const int gi   = bid * NTHR + tid;
    const int lane = tid & 31;
    const int wid  = tid >> 5;
    const int wslot = wid * 16;
    const int gw   = bid * (NTHR / 32) + wid;

    // ---- P0: zero hist, init minbits ----
    if (gi < 2 * NBINS) g_hist[gi] = 0;
    if (gi < 2 * NPTS) (&g_minbits[0][0])[gi] = 0x7f800000u;
    gsync(1 * NBLK);

    // ---- P1: code + histogram ----
    int my_s = -1;
    unsigned my_c = 0;
    float mx = 0.f, myy = 0.f, mz = 0.f;
    if (gi < 2 * NPTS) {
        my_s = gi >> 14;
        int p = gi & (NPTS - 1);
        const float* src = my_s ? gt : pred;
        mx = src[3 * p]; myy = src[3 * p + 1]; mz = src[3 * p + 2];
        my_c = morton(mx, myy, mz);
        atomicAdd(&g_hist[my_s * NBINS + my_c], 1u);
    }
    gsync(2 * NBLK);

    // ---- P2: block-local exclusive scan (128 blocks x 512 bins) ----
    unsigned lexcl = 0;
    if (bid < 128) {
        unsigned h = (tid < 512) ? __ldcg(&g_hist[bid * 512 + tid]) : 0u;
        if (tid < 512) sscan[tid] = h;
        __syncthreads();
        for (int d = 1; d < 512; d <<= 1) {
            unsigned v = (tid >= d && tid < 512) ? sscan[tid - d] : 0u;
            __syncthreads();
            if (tid < 512) sscan[tid] += v;
            __syncthreads();
        }
        if (tid < 512) lexcl = sscan[tid] - h;
        if (tid == 511) g_part[bid] = sscan[511];
    }
    gsync(3 * NBLK);

    // ---- P2b: chunk prefixes + offsets ----
    if (bid < 128) {
        if (tid < 128) sscan[tid] = __ldcg(&g_part[tid]);
        __syncthreads();
        for (int d = 1; d < 128; d <<= 1) {
            unsigned v = (tid >= d && tid < 128) ? sscan[tid - d] : 0u;
            __syncthreads();
            if (tid < 128) sscan[tid] += v;
            __syncthreads();
        }
        unsigned prefix = (bid == 0) ? 0u : sscan[bid - 1];
        unsigned adj = (bid >= 64) ? (unsigned)NPTS : 0u;
        if (tid < 512) g_offs[bid * 512 + tid] = lexcl + prefix - adj;
    }
    gsync(4 * NBLK);

    // ---- P3: scatter ----
    if (my_s >= 0) {
        unsigned pos = atomicAdd(&g_offs[my_s * NBINS + my_c], 1u);
        g_sorted[my_s][pos] =
            make_float4(mx, myy, mz, 0.5f * (mx * mx + myy * myy + mz * mz));
    }
    gsync(5 * NBLK);

    // ---- P4: group AABBs (warps 0..1023) + seeds (warps 1024..2047) ----
    if (gw < 2 * NGRP) {
        int s = gw >= NGRP, g = gw & (NGRP - 1);
        float4 pv = g_sorted[s][g * 32 + lane];
        float lx = pv.x, ly = pv.y, lz = pv.z;
        float hx = pv.x, hy = pv.y, hz = pv.z;
#pragma unroll
        for (int d = 16; d > 0; d >>= 1) {
            lx = fminf(lx, __shfl_xor_sync(0xffffffffu, lx, d));
            ly = fminf(ly, __shfl_xor_sync(0xffffffffu, ly, d));
            lz = fminf(lz, __shfl_xor_sync(0xffffffffu, lz, d));
            hx = fmaxf(hx, __shfl_xor_sync(0xffffffffu, hx, d));
            hy = fmaxf(hy, __shfl_xor_sync(0xffffffffu, hy, d));
            hz = fmaxf(hz, __shfl_xor_sync(0xffffffffu, hz, d));
        }
        if (lane == 0) {
            g_gaabb[s][g][0] = make_float4(lx, ly, lz, 0.0f);
            g_gaabb[s][g][1] = make_float4(hx, hy, hz, 0.0f);
        }
    } else if (gw < 4 * NGRP) {
        int id = gw - 2 * NGRP;
        int dir = id >= NGRP, xg = id & (NGRP - 1);
        int sy = dir ^ 1;
        float4 xp = g_sorted[dir][xg * 32 + lane];
        float x2 = 2.0f * xp.w;
        float ma = INFF, mb = INFF;
        int s0 = max(xg - 1, 0), s1 = min(xg + 1, NGRP - 1);
        for (int g = s0; g <= s1; ++g) EVAL1(sy, g);
        float d2 = fmaxf(fmaf(2.0f, fminf(ma, mb), x2), 0.0f);
        atomicMin(&g_minbits[dir][xg * 32 + lane], __float_as_uint(d2));
    }
    gsync(6 * NBLK);

    // ---- P5: AABBs into smem ----
    for (int i = tid; i < 2 * NGRP; i += NTHR) {
        int s = i >= NGRP, g = i & (NGRP - 1);
        sb[s][g][0] = g_gaabb[s][g][0];
        sb[s][g][1] = g_gaabb[s][g][1];
    }
    __syncthreads();
    if (tid < 2 * NSUP) {
        int s = tid >= NSUP, i = tid & (NSUP - 1);
        float4 lo = sb[s][i * 8][0];
        float4 hi = sb[s][i * 8][1];
#pragma unroll
        for (int k = 1; k < 8; ++k) {
            float4 a = sb[s][i * 8 + k][0];
            float4 b = sb[s][i * 8 + k][1];
            lo.x = fminf(lo.x, a.x); lo.y = fminf(lo.y, a.y); lo.z = fminf(lo.z, a.z);
            hi.x = fmaxf(hi.x, b.x); hi.y = fmaxf(hi.y, b.y); hi.z = fmaxf(hi.z, b.z);
        }
        ssb[s][i][0] = lo;
        ssb[s][i][1] = hi;
    }
    __syncthreads();

    // ---- P6: work-queue sweep; unit = (dir, xg-pair, ychunk of 8 supergroups) ----
    for (;;) {
        unsigned uid;
        if (lane == 0) uid = atomicAdd(&g_work, 1u);
        uid = __shfl_sync(0xffffffffu, uid, 0);
        if (uid >= NUNITS) break;

        const int dir = uid & 1;
        const int xgp = (uid >> 1) & (NXP - 1);
        const int yc  = uid >> 9;            // 0..7
        const int sy  = dir ^ 1;
        const int pb  = xgp * 64;
        const int k0  = 2 * xgp, k1 = 2 * xgp + 1;  // covered by BOTH seeds

        const float4 xp0 = g_sorted[dir][pb + lane];
        const float4 xp1 = g_sorted[dir][pb + 32 + lane];
        const float x2a = 2.0f * xp0.w, x2b = 2.0f * xp1.w;
        float ub2a = __uint_as_float(__ldcg(&g_minbits[dir][pb + lane]));
        float ub2b = __uint_as_float(__ldcg(&g_minbits[dir][pb + 32 + lane]));
        float ma0 = INFF, mb0 = INFF, ma1 = INFF, mb1 = INFF;

        for (int i = 0; i < 8; ++i) {
            int sg = yc * 8 + i;
            bool hit = (boxd2(xp0.x, xp0.y, xp0.z, ssb[sy][sg][0], ssb[sy][sg][1]) <= ub2a) ||
                       (boxd2(xp1.x, xp1.y, xp1.z, ssb[sy][sg][0], ssb[sy][sg][1]) <= ub2b);
            if (!__any_sync(0xffffffffu, hit)) continue;
            unsigned gm = 0;
#pragma unroll
            for (int b = 0; b < 8; ++b) {
                int g = sg * 8 + b;
                if (g == k0 || g == k1) continue;   // folded in by seeds already
                if ((boxd2(xp0.x, xp0.y, xp0.z, sb[sy][g][0], sb[sy][g][1]) <= ub2a) ||
                    (boxd2(xp1.x, xp1.y, xp1.z, sb[sy][g][0], sb[sy][g][1]) <= ub2b))
                    gm |= 1u << b;
            }
            gm = __reduce_or_sync(0xffffffffu, gm);
            while (gm) {
                int b = __ffs(gm) - 1;
                gm &= gm - 1;
                EVAL2(sy, sg * 8 + b);
                ub2a = fminf(ub2a, fmaxf(fmaf(2.0f, fminf(ma0, mb0), x2a), 0.0f));
                ub2b = fminf(ub2b, fmaxf(fmaf(2.0f, fminf(ma1, mb1), x2b), 0.0f));
            }
        }
        if (fminf(ma0, mb0) < INFF)
            atomicMin(&g_minbits[dir][pb + lane],
                      __float_as_uint(fmaxf(fmaf(2.0f, fminf(ma0, mb0), x2a), 0.0f)));
        if (fminf(ma1, mb1) < INFF)
            atomicMin(&g_minbits[dir][pb + 32 + lane],
                      __float_as_uint(fmaxf(fmaf(2.0f, fminf(ma1, mb1), x2b), 0.0f)));
    }

    // ---- ticket: last block reduces + resets counters ----
    __threadfence();
    __syncthreads();
    if (tid == 0) s_ticket = atomicAdd(&g_done, 1u);
    __syncthreads();
    if (s_ticket == NBLK - 1) {
        if (tid == 0) { g_bar = 0; g_work = 0; g_done = 0; }
        __threadfence();
        float* red = (float*)stage;   // stage unused past this point
        float s = 0.0f;
        const unsigned* mb32 = &g_minbits[0][0];
        for (int i = tid; i < 2 * NPTS; i += NTHR)
            s += sqrtf(__uint_as_float(__ldcg(&mb32[i])));
        red[tid] = s;
        __syncthreads();
        for (int w = NTHR / 2; w > 0; w >>= 1) {
            if (tid < w) red[tid] += red[tid + w];
            __syncthreads();
        }
        if (tid == 0) out[0] = red[0] * (1.0f / (float)NPTS);
    }
}

extern "C" void kernel_launch(void* const* d_in, const int* in_sizes, int n_in,
                              void* d_out, int out_size) {
    const float* pred = (const float*)d_in[0];
    const float* gt   = (const float*)d_in[1];
    float* out = (float*)d_out;
    k_all<<<NBLK, NTHR>>>(pred, gt, out);
}